// round 3
// baseline (speedup 1.0000x reference)
#include <cuda_runtime.h>

#define NTHREADS 128

// Species row 0 = H, row 1 = O (padded: mu=0, sg=1)
__constant__ float c_mu[2][9] = {
  {-0.0013891633279463555f, 0.052817133273316774f, 0.139812833597163f, 0.04197082575153015f,
    0.f, 0.f, 0.f, 0.f, 0.f},
  { 0.3869724094534165f, 1.1195726605859562f, 4.597656411500856f, 4.18116756869605f,
   -0.777753667038269f, 0.8991094564592526f, 0.25287442792706855f, 0.f, 0.f}
};
__constant__ float c_sg[2][9] = {
  {0.014984132924379046f, 0.06597323056314336f, 0.05229082868259066f, 0.10317217531939492f,
   1.f, 1.f, 1.f, 1.f, 1.f},
  {0.01648580936203453f, 0.04360467004470585f, 0.10939958699162289f, 0.1452881891452822f,
   0.24744978852384295f, 0.6757096584771374f, 0.15629951845443388f, 1.f, 1.f}
};

// om vector -> coefficient indices. Vectors 0-3: p (9+3v+k).
// Vectors 4-7: d[v-4][{0,2,5}] (D_REORDER[0:3] = 0,2,5), vectors 8-11: d[v-8][{4,3,1}].
__constant__ int c_omidx[12][3] = {
  { 9, 10, 11}, {12, 13, 14}, {15, 16, 17}, {18, 19, 20},
  {21, 23, 26}, {27, 29, 32}, {33, 35, 38}, {39, 41, 44},
  {25, 24, 22}, {31, 30, 28}, {37, 36, 34}, {43, 42, 40}
};

// triu_indices(12, k=1) row-major
__constant__ unsigned char c_pi[66] = {
  0,0,0,0,0,0,0,0,0,0,0,
  1,1,1,1,1,1,1,1,1,1,
  2,2,2,2,2,2,2,2,2,
  3,3,3,3,3,3,3,3,
  4,4,4,4,4,4,4,
  5,5,5,5,5,5,
  6,6,6,6,6,
  7,7,7,7,
  8,8,8,
  9,9,
  10
};
__constant__ unsigned char c_pj[66] = {
  1,2,3,4,5,6,7,8,9,10,11,
  2,3,4,5,6,7,8,9,10,11,
  3,4,5,6,7,8,9,10,11,
  4,5,6,7,8,9,10,11,
  5,6,7,8,9,10,11,
  6,7,8,9,10,11,
  7,8,9,10,11,
  8,9,10,11,
  9,10,11,
  10,11,
  11
};

// cos/sin of Z_k = k*pi/7, k = 0..7
__constant__ float c_cz[8] = { 1.0f,  0.90096887f,  0.62348980f,  0.22252093f,
                              -0.22252093f, -0.62348980f, -0.90096887f, -1.0f };
__constant__ float c_sz[8] = { 0.0f,  0.43388374f,  0.78183148f,  0.97492791f,
                               0.97492791f,  0.78183148f,  0.43388374f,  0.0f };

// Anchored Gaussian-row recurrence: row[i] = exp(-eta*(x - (lo + i*delta))^2)
// for i = 0..N-1, using 3 exps total. Anchored at nearest shift so both
// outward ratio chains are <= 1 (monotone decay, correct underflow at the tails).
__device__ __forceinline__ void gauss_row(
    float x, float lo, float delta, float inv_delta,
    float eta, float e2d /*2*eta*delta*/, float ed2 /*eta*delta^2*/,
    float q /*exp(-2*eta*delta^2)*/, int N, float* __restrict__ row)
{
    float af = (x - lo) * inv_delta;
    int a = __float2int_rn(af);
    a = a < 0 ? 0 : (a > N - 1 ? N - 1 : a);
    float t = x - fmaf((float)a, delta, lo);
    float Ea = __expf(-eta * t * t);
    float ru = __expf(fmaf( e2d, t, -ed2));   // ratio E_{a+1}/E_a
    float rd = __expf(fmaf(-e2d, t, -ed2));   // ratio E_{a-1}/E_a
    row[a] = Ea;
    float E = Ea;
    for (int i = a; i < N - 1; ++i) { E *= ru; row[i + 1] = E; ru *= q; }
    E = Ea;
    for (int i = a; i > 0; --i)     { E *= rd; row[i - 1] = E; rd *= q; }
}

__global__ __launch_bounds__(NTHREADS)
void aev_kernel(const float* __restrict__ coeff, const int* __restrict__ species,
                float* __restrict__ out)
{
    __shared__ float sh_raw[45];
    __shared__ int   sh_sp;
    __shared__ __align__(16) float sh_sr[336];      // 144 s_aev + 192 r_aev
    __shared__ float sh_dist[12];
    __shared__ float sh_u[12][3];
    __shared__ float sh_f1[66 * 8];                 // holds 2*f1 (premultiplied)
    __shared__ __align__(16) float sh_f2[66 * 8];

    const int blk = blockIdx.x;      // one block per atom (nconf*natoms blocks)
    const int t   = threadIdx.x;

    // ---- stage 1: load 45 coefficients + species ----
    const float* cin = coeff + (size_t)blk * 45;
    if (t < 45) sh_raw[t] = cin[t];
    if (t == 64) sh_sp = (species[blk] == 8) ? 1 : 0;
    __syncthreads();

    // ---- stage 2: om vectors / distances / unit vectors, plus s_aev chains ----
    if (t < 12) {
        float x = sh_raw[c_omidx[t][0]];
        float y = sh_raw[c_omidx[t][1]];
        float z = sh_raw[c_omidx[t][2]];
        float dot = fmaf(x, x, fmaf(y, y, z * z));
        float d   = sqrtf(dot);
        bool zm = (fabsf(x) < 1e-12f) && (fabsf(y) < 1e-12f) && (fabsf(z) < 1e-12f);
        float inv = zm ? 0.0f : rsqrtf(dot);
        sh_dist[t] = d;
        sh_u[t][0] = x * inv;
        sh_u[t][1] = y * inv;
        sh_u[t][2] = z * inv;
    } else if (t >= 32 && t < 41) {
        // s_aev: eta=4, shifts linspace(-4,4,16), delta=8/15
        int k = t - 32;
        int sp = sh_sp;
        float x = (sh_raw[k] - c_mu[sp][k]) / c_sg[sp][k];
        gauss_row(x, -4.0f, 0.53333333f, 1.875f, 4.0f,
                  4.2666667f, 1.1377778f, 0.10273989f, 16, &sh_sr[k * 16]);
    }
    __syncthreads();

    // ---- stage 3: pair terms (f1 via analytic cos(acos(c)-Z), f2 via chain) + r_aev chains ----
    if (t < 66) {
        int i = c_pi[t], j = c_pj[t];
        float c = 0.9999f * fmaf(sh_u[i][0], sh_u[j][0],
                      fmaf(sh_u[i][1], sh_u[j][1], sh_u[i][2] * sh_u[j][2]));
        float sq = sqrtf(fmaxf(0.0f, fmaf(-c, c, 1.0f)));   // sin(acos(c))
        float av = 0.5f * (sh_dist[i] + sh_dist[j]);
        #pragma unroll
        for (int z = 0; z < 8; ++z) {
            float ct = fmaf(c, c_cz[z], sq * c_sz[z]);      // cos(theta - Z_z)
            float b  = fmaf(0.5f, ct, 0.5f);                // (1+cos)/2 in [0,1]
            float b2 = b * b;
            float b4 = b2 * b2;
            sh_f1[t * 8 + z] = 2.0f * (b4 * b4);            // 2 * ((1+cos)/2)^8
        }
        // f2: eta=8, shifts linspace(0,2,8), delta=2/7
        gauss_row(av, 0.0f, 0.28571429f, 3.5f, 8.0f,
                  4.5714286f, 0.65306122f, 0.27086851f, 8, &sh_f2[t * 8]);
    } else if (t < 78) {
        // r_aev: eta=4, shifts linspace(0,2,16), delta=2/15
        int k = t - 66;
        gauss_row(sh_dist[k], 0.0f, 0.13333333f, 7.5f, 4.0f,
                  1.0666667f, 0.071111111f, 0.86742845f, 16, &sh_sr[144 + k * 16]);
    }
    __syncthreads();

    // ---- stage 4: streaming (evict-first) float4 stores: 84 (s+r) + 1056 angular ----
    float4* out4 = reinterpret_cast<float4*>(out) + (size_t)blk * 1140;
    if (t < 84) __stcs(&out4[t], reinterpret_cast<const float4*>(sh_sr)[t]);

    const float4* f2v = reinterpret_cast<const float4*>(sh_f2);
    #pragma unroll
    for (int it = 0; it < 9; ++it) {
        int w = it * 128 + t;
        if (w < 1056) {
            int pair = w >> 4;
            int rem  = w & 15;                      // = z*2 + half
            float f1 = sh_f1[pair * 8 + (rem >> 1)];  // already includes the 2x
            float4 f2 = f2v[pair * 2 + (rem & 1)];
            float4 o;
            o.x = f1 * f2.x; o.y = f1 * f2.y; o.z = f1 * f2.z; o.w = f1 * f2.w;
            __stcs(&out4[84 + w], o);               // element = 336 + pair*64 + z*8 + a
        }
    }
}

extern "C" void kernel_launch(void* const* d_in, const int* in_sizes, int n_in,
                              void* d_out, int out_size)
{
    const float* coeff   = (const float*)d_in[0];   // (nconf, natoms, 45) f32
    const int*   species = (const int*)d_in[1];     // (nconf, natoms) i32
    float*       out     = (float*)d_out;           // (nconf, natoms, 4560) f32
    int nblk = in_sizes[1];                         // nconf * natoms atoms
    aev_kernel<<<nblk, NTHREADS>>>(coeff, species, out);
}

// round 4
// speedup vs baseline: 1.0780x; 1.0780x over previous
#include <cuda_runtime.h>

#define NTHREADS 128

// Species row 0 = H, row 1 = O (padded: mu=0, sg=1)
__constant__ float c_mu[2][9] = {
  {-0.0013891633279463555f, 0.052817133273316774f, 0.139812833597163f, 0.04197082575153015f,
    0.f, 0.f, 0.f, 0.f, 0.f},
  { 0.3869724094534165f, 1.1195726605859562f, 4.597656411500856f, 4.18116756869605f,
   -0.777753667038269f, 0.8991094564592526f, 0.25287442792706855f, 0.f, 0.f}
};
__constant__ float c_sg[2][9] = {
  {0.014984132924379046f, 0.06597323056314336f, 0.05229082868259066f, 0.10317217531939492f,
   1.f, 1.f, 1.f, 1.f, 1.f},
  {0.01648580936203453f, 0.04360467004470585f, 0.10939958699162289f, 0.1452881891452822f,
   0.24744978852384295f, 0.6757096584771374f, 0.15629951845443388f, 1.f, 1.f}
};

// om vector -> coefficient indices. Vectors 0-3: p (9+3v+k).
// Vectors 4-7: d[v-4][{0,2,5}] (D_REORDER[0:3] = 0,2,5), vectors 8-11: d[v-8][{4,3,1}].
__constant__ int c_omidx[12][3] = {
  { 9, 10, 11}, {12, 13, 14}, {15, 16, 17}, {18, 19, 20},
  {21, 23, 26}, {27, 29, 32}, {33, 35, 38}, {39, 41, 44},
  {25, 24, 22}, {31, 30, 28}, {37, 36, 34}, {43, 42, 40}
};

// triu_indices(12, k=1) row-major
__constant__ unsigned char c_pi[66] = {
  0,0,0,0,0,0,0,0,0,0,0,
  1,1,1,1,1,1,1,1,1,1,
  2,2,2,2,2,2,2,2,2,
  3,3,3,3,3,3,3,3,
  4,4,4,4,4,4,4,
  5,5,5,5,5,5,
  6,6,6,6,6,
  7,7,7,7,
  8,8,8,
  9,9,
  10
};
__constant__ unsigned char c_pj[66] = {
  1,2,3,4,5,6,7,8,9,10,11,
  2,3,4,5,6,7,8,9,10,11,
  3,4,5,6,7,8,9,10,11,
  4,5,6,7,8,9,10,11,
  5,6,7,8,9,10,11,
  6,7,8,9,10,11,
  7,8,9,10,11,
  8,9,10,11,
  9,10,11,
  10,11,
  11
};

// cos/sin of Z_k = k*pi/7, k = 0..7
__constant__ float c_cz[8] = { 1.0f,  0.90096887f,  0.62348980f,  0.22252093f,
                              -0.22252093f, -0.62348980f, -0.90096887f, -1.0f };
__constant__ float c_sz[8] = { 0.0f,  0.43388374f,  0.78183148f,  0.97492791f,
                               0.97492791f,  0.78183148f,  0.43388374f,  0.0f };

__global__ __launch_bounds__(NTHREADS)
void aev_kernel(const float* __restrict__ coeff, const int* __restrict__ species,
                float* __restrict__ out)
{
    __shared__ float sh_sn[9];                      // normalized s coefficients
    __shared__ float sh_dist[12];
    __shared__ float sh_u[12][3];
    __shared__ float sh_c[66], sh_sq[66], sh_av[66];
    __shared__ __align__(16) float sh_sr[336];      // 144 s_aev + 192 r_aev
    __shared__ float sh_f1[528];                    // 2*f1 (premultiplied), [pair][z]
    __shared__ __align__(16) float sh_f2[528];      // [pair][a]

    const int blk = blockIdx.x;      // one block per atom
    const int t   = threadIdx.x;
    const float* cin = coeff + (size_t)blk * 45;

    // ---- stage A: each thread loads what it needs directly (no staging sync) ----
    if (t < 12) {
        float x = cin[c_omidx[t][0]];
        float y = cin[c_omidx[t][1]];
        float z = cin[c_omidx[t][2]];
        float dot = fmaf(x, x, fmaf(y, y, z * z));
        float d   = sqrtf(dot);
        bool zm = (fabsf(x) < 1e-12f) && (fabsf(y) < 1e-12f) && (fabsf(z) < 1e-12f);
        float inv = zm ? 0.0f : rsqrtf(dot);
        sh_dist[t] = d;
        sh_u[t][0] = x * inv;
        sh_u[t][1] = y * inv;
        sh_u[t][2] = z * inv;
    } else if (t >= 32 && t < 41) {
        int k  = t - 32;
        int sp = (species[blk] == 8) ? 1 : 0;
        sh_sn[k] = (cin[k] - c_mu[sp][k]) / c_sg[sp][k];
    }
    __syncthreads();

    // ---- stage B: per-pair cos(theta), sin(theta), avg distance ----
    if (t < 66) {
        int i = c_pi[t], j = c_pj[t];
        float c = 0.9999f * fmaf(sh_u[i][0], sh_u[j][0],
                      fmaf(sh_u[i][1], sh_u[j][1], sh_u[i][2] * sh_u[j][2]));
        sh_c[t]  = c;
        sh_sq[t] = sqrtf(fmaxf(0.0f, fmaf(-c, c, 1.0f)));   // sin(acos(c))
        sh_av[t] = 0.5f * (sh_dist[i] + sh_dist[j]);
    }
    __syncthreads();

    // ---- stage C: fully parallel element evaluation (1392 independent elements) ----
    // [0,144)    s_aev:  k=w/16, i=w%16,  exp(-4*(sn[k] - (-4 + i*8/15))^2)
    // [144,336)  r_aev:  k, i,            exp(-4*(dist[k] - i*2/15)^2)
    // [336,864)  f2:     p=v/8, a=v%8,    exp(-8*(av[p] - a*2/7)^2)
    // [864,1392) f1:     p, z,            2*((1 + cos(theta - Z_z))/2)^8  (analytic)
    #pragma unroll
    for (int it = 0; it < 11; ++it) {
        int w = it * 128 + t;
        if (w < 144) {
            int k = w >> 4, i = w & 15;
            float x = sh_sn[k] - fmaf((float)i, 0.53333333f, -4.0f);
            sh_sr[w] = __expf(-4.0f * x * x);
        } else if (w < 336) {
            int v = w - 144; int k = v >> 4, i = v & 15;
            float x = sh_dist[k] - (float)i * 0.13333333f;
            sh_sr[w] = __expf(-4.0f * x * x);
        } else if (w < 864) {
            int v = w - 336; int p = v >> 3, a = v & 7;
            float x = sh_av[p] - (float)a * 0.28571429f;
            sh_f2[v] = __expf(-8.0f * x * x);
        } else if (w < 1392) {
            int v = w - 864; int p = v >> 3, z = v & 7;
            float ct = fmaf(sh_c[p], c_cz[z], sh_sq[p] * c_sz[z]);  // cos(theta - Z_z)
            float b  = fmaf(0.5f, ct, 0.5f);
            float b2 = b * b;
            float b4 = b2 * b2;
            sh_f1[v] = 2.0f * (b4 * b4);
        }
    }
    __syncthreads();

    // ---- stage D: coalesced float4 stores: 84 (s+r) + 1056 angular per atom ----
    float4* out4 = reinterpret_cast<float4*>(out) + (size_t)blk * 1140;
    if (t < 84) out4[t] = reinterpret_cast<const float4*>(sh_sr)[t];

    const float4* f2v = reinterpret_cast<const float4*>(sh_f2);
    #pragma unroll
    for (int it = 0; it < 9; ++it) {
        int w = it * 128 + t;
        if (w < 1056) {
            int pair = w >> 4;
            int rem  = w & 15;                        // = z*2 + half
            float f1 = sh_f1[pair * 8 + (rem >> 1)];  // includes the 2x
            float4 f2 = f2v[pair * 2 + (rem & 1)];
            float4 o;
            o.x = f1 * f2.x; o.y = f1 * f2.y; o.z = f1 * f2.z; o.w = f1 * f2.w;
            out4[84 + w] = o;                         // element = 336 + pair*64 + z*8 + a
        }
    }
}

extern "C" void kernel_launch(void* const* d_in, const int* in_sizes, int n_in,
                              void* d_out, int out_size)
{
    const float* coeff   = (const float*)d_in[0];   // (nconf, natoms, 45) f32
    const int*   species = (const int*)d_in[1];     // (nconf, natoms) i32
    float*       out     = (float*)d_out;           // (nconf, natoms, 4560) f32
    int nblk = in_sizes[1];                         // nconf * natoms atoms
    aev_kernel<<<nblk, NTHREADS>>>(coeff, species, out);
}